// round 13
// baseline (speedup 1.0000x reference)
#include <cuda_runtime.h>
#include <math.h>
#include <stdint.h>

// ---------------- problem constants ----------------
constexpr int Bb   = 32;
constexpr int N1   = 256;
constexpr int D1   = 256;
constexpr int NH   = 8;
constexpr int KD   = 256;
constexpr int HID  = 1024;
constexpr int LAY  = 8;
constexpr int ROWS = Bb * N1;      // 8192
constexpr int QC   = NH * KD;      // 2048
constexpr float LN_EPS = 1e-3f;

// ---------------- scratch (static device memory; no allocation) ----------------
__device__ float g_patch[ROWS * D1];
__device__ float g_enc  [ROWS * D1];
__device__ float g_encr [ROWS * D1];         // tf32-rounded copy of enc (GEMM A operand)
__device__ float g_q    [ROWS * QC];
__device__ float g_k    [ROWS * QC];
__device__ float g_v    [ROWS * QC];
__device__ float g_attn [Bb * NH * N1 * N1];
__device__ float g_o    [ROWS * QC];
__device__ float g_a    [ROWS * D1];
__device__ float g_f1   [ROWS * HID];
// tf32-rounded weights (refreshed every call)
__device__ float g_wr_in[D1 * D1];
__device__ float g_wr_q [LAY * D1 * QC];
__device__ float g_wr_k [LAY * D1 * QC];
__device__ float g_wr_v [LAY * D1 * QC];
__device__ float g_wr_o [LAY * QC * D1];
__device__ float g_wr_1 [LAY * D1 * HID];
__device__ float g_wr_2 [LAY * HID * D1];

// ---------------- helpers ----------------
__device__ __forceinline__ float gelu_exact(float x) {
    return 0.5f * x * (1.0f + erff(x * 0.7071067811865476f));
}
__device__ __forceinline__ uint32_t f2tf32(float x) {
    uint32_t r;
    asm("cvt.rna.tf32.f32 %0, %1;" : "=r"(r) : "f"(x));
    return r;
}
__device__ __forceinline__ float roundtf(float x) {
    return __uint_as_float(f2tf32(x));
}
__device__ __forceinline__ void mma_tf32(float c[4], const uint32_t a[4], const uint32_t b[2]) {
    asm volatile(
        "mma.sync.aligned.m16n8k8.row.col.f32.tf32.tf32.f32 "
        "{%0,%1,%2,%3}, {%4,%5,%6,%7}, {%8,%9}, {%0,%1,%2,%3};\n"
        : "+f"(c[0]), "+f"(c[1]), "+f"(c[2]), "+f"(c[3])
        : "r"(a[0]), "r"(a[1]), "r"(a[2]), "r"(a[3]),
          "r"(b[0]), "r"(b[1]));
}
__device__ __forceinline__ void cp_async16(uint32_t dst_smem, const void* src) {
    asm volatile("cp.async.cg.shared.global [%0], [%1], 16;" :: "r"(dst_smem), "l"(src));
}
__device__ __forceinline__ void cp_commit() {
    asm volatile("cp.async.commit_group;" ::: "memory");
}
template<int N>
__device__ __forceinline__ void cp_wait() {
    asm volatile("cp.async.wait_group %0;" :: "n"(N) : "memory");
}

// ---------------- TF32 tensor-core GEMM: inputs pre-rounded, BK=32, cp.async x2 ----------------
// C[z] = act( alpha * A[z] @ op(B[z]) + bias ); all A/B elements already tf32-rounded.
// A: [M,K] row-major.  NN: B [K,N];  NT: B [N,K] (computes A.B^T)
// Block 128x128x32, 8 warps (2m x 4n), warp tile 64x32, mma m16n8k8.
// OMODE: 0 = store full fp32; 1 = store tf32-rounded; 2 = dual (C full, Cr rounded)
#define BM 128
#define BN 128
#define BK 32
#define AS_LD 36      // [m][k] stride 36 floats: bank = 4*qrow+qcol, conflict-free; 16B-aligned
#define BS_LD 136     // NN [k][n] stride 136: bank = 8*qcol+qrow (+8u), conflict-free
#define A_STG 4608    // 128*36 floats per A stage
#define B_STG 4608    // max(32*136=4352, 128*36=4608) floats per B stage
#define SMEM_GEMM ((2 * A_STG + 2 * B_STG) * 4)   // 73728 bytes

template<bool TRANS_B, bool GELU, int OMODE>
__global__ __launch_bounds__(256, 2)
void mma_gemm_kernel(const float* __restrict__ A, const float* __restrict__ B,
                     const float* __restrict__ bias, float* __restrict__ C,
                     float* __restrict__ Cr,
                     int K, int lda, int ldb, int ldc,
                     long sA1, long sA2, long sB1, long sB2, long sC1, long sC2,
                     int nb2, float alpha)
{
    extern __shared__ float smem[];
    const int z  = blockIdx.z;
    const int z1 = z / nb2, z2 = z - z1 * nb2;
    A += (long)z1 * sA1 + (long)z2 * sA2;
    B += (long)z1 * sB1 + (long)z2 * sB2;
    C += (long)z1 * sC1 + (long)z2 * sC2;
    if (OMODE == 2) Cr += (long)z1 * sC1 + (long)z2 * sC2;

    const int tid  = threadIdx.x;
    const int lane = tid & 31;
    const int wid  = tid >> 5;
    const int wm   = wid >> 2;           // 0..1
    const int wn   = wid & 3;            // 0..3
    const int row0 = blockIdx.y * BM;
    const int col0 = blockIdx.x * BN;

    const int a_row = tid >> 3;          // 0..31
    const int a_col = (tid & 7) << 2;    // 0,4,...,28
    const int b_row = tid >> 5;          // 0..7
    const int b_col = (tid & 31) << 2;   // 0..124

    const int qrow = lane >> 2;          // 0..7
    const int qcol = lane & 3;           // 0..3

    const uint32_t sbase = (uint32_t)__cvta_generic_to_shared(smem);
    const uint32_t offA[2] = {0u, A_STG};
    const uint32_t offB[2] = {2u * A_STG, 2u * A_STG + B_STG};

    float acc[4][4][4];
#pragma unroll
    for (int t = 0; t < 4; t++)
#pragma unroll
        for (int u = 0; u < 4; u++)
#pragma unroll
            for (int r = 0; r < 4; r++) acc[t][u][r] = 0.f;

    const int steps = K >> 5;

    auto fill = [&](int buf, int k0) {
#pragma unroll
        for (int r = 0; r < 4; r++) {
            int m = a_row + r * 32;
            cp_async16(sbase + (offA[buf] + (uint32_t)(m * AS_LD + a_col)) * 4,
                       A + (long)(row0 + m) * lda + k0 + a_col);
        }
        if (!TRANS_B) {
#pragma unroll
            for (int r = 0; r < 4; r++) {
                int kk = b_row + r * 8;
                cp_async16(sbase + (offB[buf] + (uint32_t)(kk * BS_LD + b_col)) * 4,
                           B + (long)(k0 + kk) * ldb + col0 + b_col);
            }
        } else {
#pragma unroll
            for (int r = 0; r < 4; r++) {
                int n = a_row + r * 32;
                cp_async16(sbase + (offB[buf] + (uint32_t)(n * AS_LD + a_col)) * 4,
                           B + (long)(col0 + n) * ldb + k0 + a_col);
            }
        }
    };

    fill(0, 0);     cp_commit();
    fill(1, BK);    cp_commit();

    for (int s = 0; s < steps; s++) {
        if (s + 1 < steps) cp_wait<1>(); else cp_wait<0>();
        __syncthreads();
        const float* Ab   = smem + offA[s & 1];
        const float* Bbuf = smem + offB[s & 1];

#pragma unroll
        for (int ks = 0; ks < BK; ks += 8) {
            uint32_t afrag[4][4];
#pragma unroll
            for (int t = 0; t < 4; t++) {
                int mb = wm * 64 + t * 16;
                afrag[t][0] = __float_as_uint(Ab[(mb + qrow)     * AS_LD + ks + qcol    ]);
                afrag[t][1] = __float_as_uint(Ab[(mb + qrow + 8) * AS_LD + ks + qcol    ]);
                afrag[t][2] = __float_as_uint(Ab[(mb + qrow)     * AS_LD + ks + qcol + 4]);
                afrag[t][3] = __float_as_uint(Ab[(mb + qrow + 8) * AS_LD + ks + qcol + 4]);
            }
            uint32_t bfrag[4][2];
#pragma unroll
            for (int u = 0; u < 4; u++) {
                int nb = wn * 32 + u * 8;
                if (!TRANS_B) {
                    bfrag[u][0] = __float_as_uint(Bbuf[(ks + qcol)     * BS_LD + nb + qrow]);
                    bfrag[u][1] = __float_as_uint(Bbuf[(ks + qcol + 4) * BS_LD + nb + qrow]);
                } else {
                    bfrag[u][0] = __float_as_uint(Bbuf[(nb + qrow) * AS_LD + ks + qcol    ]);
                    bfrag[u][1] = __float_as_uint(Bbuf[(nb + qrow) * AS_LD + ks + qcol + 4]);
                }
            }
#pragma unroll
            for (int t = 0; t < 4; t++)
#pragma unroll
                for (int u = 0; u < 4; u++)
                    mma_tf32(acc[t][u], afrag[t], bfrag[u]);
        }
        __syncthreads();
        if (s + 2 < steps) { fill(s & 1, (s + 2) << 5); cp_commit(); }
    }

#pragma unroll
    for (int t = 0; t < 4; t++) {
        int r0 = row0 + wm * 64 + t * 16 + qrow;
#pragma unroll
        for (int u = 0; u < 4; u++) {
            int n = col0 + wn * 32 + u * 8 + qcol * 2;
            float bx = bias ? bias[n + 0] : 0.f;
            float by = bias ? bias[n + 1] : 0.f;
            float2 v0, v1;
            v0.x = fmaf(acc[t][u][0], alpha, bx);
            v0.y = fmaf(acc[t][u][1], alpha, by);
            v1.x = fmaf(acc[t][u][2], alpha, bx);
            v1.y = fmaf(acc[t][u][3], alpha, by);
            if (GELU) {
                v0.x = gelu_exact(v0.x); v0.y = gelu_exact(v0.y);
                v1.x = gelu_exact(v1.x); v1.y = gelu_exact(v1.y);
            }
            if (OMODE == 1) {
                v0.x = roundtf(v0.x); v0.y = roundtf(v0.y);
                v1.x = roundtf(v1.x); v1.y = roundtf(v1.y);
            }
            *(float2*)(C + (long)r0 * ldc + n)       = v0;
            *(float2*)(C + (long)(r0 + 8) * ldc + n) = v1;
            if (OMODE == 2) {
                float2 w0, w1;
                w0.x = roundtf(v0.x); w0.y = roundtf(v0.y);
                w1.x = roundtf(v1.x); w1.y = roundtf(v1.y);
                *(float2*)(Cr + (long)r0 * ldc + n)       = w0;
                *(float2*)(Cr + (long)(r0 + 8) * ldc + n) = w1;
            }
        }
    }
}

// ---------------- fused QK^T + softmax, 512 threads (16 warps, 2m x 8n, warp 64x32) ----------------
// Per (b,h): block covers 128 rows x 256 cols (full attention rows). NT GEMM then row softmax.
// acc = 64 floats/thread -> fits 128-reg cap at 512 threads; 4 warps/SMSP during MMA.
#define QS_BSTG (256 * AS_LD)                                // 9216 floats per B stage
#define SMEM_QS ((2 * A_STG + 2 * QS_BSTG) * 4)              // 110592 bytes

__global__ __launch_bounds__(512, 1)
void qk_softmax_kernel(const float* __restrict__ Q, const float* __restrict__ Kmat,
                       float* __restrict__ P, float alpha)
{
    extern __shared__ float smem[];
    const int z = blockIdx.z;                 // b*NH + h
    const int b = z >> 3, h = z & 7;
    const float* A = Q    + (long)b * N1 * QC + (long)h * KD;
    const float* B = Kmat + (long)b * N1 * QC + (long)h * KD;
    float* C = P + (long)z * N1 * N1;

    const int tid  = threadIdx.x;
    const int lane = tid & 31;
    const int wid  = tid >> 5;               // 0..15
    const int wm   = wid >> 3;               // 0..1
    const int wn   = wid & 7;                // 0..7
    const int row0 = blockIdx.y * BM;

    const int qrow = lane >> 2;
    const int qcol = lane & 3;

    const uint32_t sbase = (uint32_t)__cvta_generic_to_shared(smem);
    const uint32_t offA[2] = {0u, A_STG};
    const uint32_t offB[2] = {2u * A_STG, 2u * A_STG + QS_BSTG};

    float acc[4][4][4];
#pragma unroll
    for (int t = 0; t < 4; t++)
#pragma unroll
        for (int u = 0; u < 4; u++)
#pragma unroll
            for (int r = 0; r < 4; r++) acc[t][u][r] = 0.f;

    const int steps = KD >> 5;               // 8

    // loaders: A 128x32 = 1024 float4 (2/thread); B 256x32 = 2048 float4 (4/thread)
    auto fill = [&](int buf, int k0) {
#pragma unroll
        for (int r = 0; r < 2; r++) {
            int idx = tid + r * 512;
            int m = idx >> 3, c4 = (idx & 7) << 2;
            cp_async16(sbase + (offA[buf] + (uint32_t)(m * AS_LD + c4)) * 4,
                       A + (long)(row0 + m) * QC + k0 + c4);
        }
#pragma unroll
        for (int r = 0; r < 4; r++) {
            int idx = tid + r * 512;
            int n = idx >> 3, c4 = (idx & 7) << 2;
            cp_async16(sbase + (offB[buf] + (uint32_t)(n * AS_LD + c4)) * 4,
                       B + (long)n * QC + k0 + c4);
        }
    };

    fill(0, 0);     cp_commit();
    fill(1, BK);    cp_commit();

    for (int s = 0; s < steps; s++) {
        if (s + 1 < steps) cp_wait<1>(); else cp_wait<0>();
        __syncthreads();
        const float* Ab   = smem + offA[s & 1];
        const float* Bbuf = smem + offB[s & 1];

#pragma unroll
        for (int ks = 0; ks < BK; ks += 8) {
            uint32_t afrag[4][4];
#pragma unroll
            for (int t = 0; t < 4; t++) {
                int mb = wm * 64 + t * 16;
                afrag[t][0] = __float_as_uint(Ab[(mb + qrow)     * AS_LD + ks + qcol    ]);
                afrag[t][1] = __float_as_uint(Ab[(mb + qrow + 8) * AS_LD + ks + qcol    ]);
                afrag[t][2] = __float_as_uint(Ab[(mb + qrow)     * AS_LD + ks + qcol + 4]);
                afrag[t][3] = __float_as_uint(Ab[(mb + qrow + 8) * AS_LD + ks + qcol + 4]);
            }
            uint32_t bfrag[4][2];
#pragma unroll
            for (int u = 0; u < 4; u++) {
                int nb = wn * 32 + u * 8;
                bfrag[u][0] = __float_as_uint(Bbuf[(nb + qrow) * AS_LD + ks + qcol    ]);
                bfrag[u][1] = __float_as_uint(Bbuf[(nb + qrow) * AS_LD + ks + qcol + 4]);
            }
#pragma unroll
            for (int t = 0; t < 4; t++)
#pragma unroll
                for (int u = 0; u < 4; u++)
                    mma_tf32(acc[t][u], afrag[t], bfrag[u]);
        }
        __syncthreads();
        if (s + 2 < steps) { fill(s & 1, (s + 2) << 5); cp_commit(); }
    }

    // ---- fused softmax over full rows of 256 (8 warps per row group) ----
#pragma unroll
    for (int t = 0; t < 4; t++)
#pragma unroll
        for (int u = 0; u < 4; u++)
#pragma unroll
            for (int r = 0; r < 4; r++) acc[t][u][r] *= alpha;

    float* red = smem;   // 128 rows x 8 warps = 1024 floats; smem free after final sync

    // pass 1: row max
    float rmax[4][2];
#pragma unroll
    for (int t = 0; t < 4; t++)
#pragma unroll
        for (int hh = 0; hh < 2; hh++) {
            float m = -INFINITY;
#pragma unroll
            for (int u = 0; u < 4; u++) {
                m = fmaxf(m, acc[t][u][hh * 2 + 0]);
                m = fmaxf(m, acc[t][u][hh * 2 + 1]);
            }
            m = fmaxf(m, __shfl_xor_sync(0xffffffffu, m, 1));
            m = fmaxf(m, __shfl_xor_sync(0xffffffffu, m, 2));
            rmax[t][hh] = m;
        }
    if (qcol == 0) {
#pragma unroll
        for (int t = 0; t < 4; t++)
#pragma unroll
            for (int hh = 0; hh < 2; hh++) {
                int row = wm * 64 + t * 16 + hh * 8 + qrow;
                red[row * 8 + wn] = rmax[t][hh];
            }
    }
    __syncthreads();
#pragma unroll
    for (int t = 0; t < 4; t++)
#pragma unroll
        for (int hh = 0; hh < 2; hh++) {
            int row = wm * 64 + t * 16 + hh * 8 + qrow;
            float m = red[row * 8 + 0];
#pragma unroll
            for (int w = 1; w < 8; w++) m = fmaxf(m, red[row * 8 + w]);
            rmax[t][hh] = m;
        }
    __syncthreads();   // before red reuse for sums

    // pass 2: exp + row sum
    float rsum[4][2];
#pragma unroll
    for (int t = 0; t < 4; t++)
#pragma unroll
        for (int hh = 0; hh < 2; hh++) {
            float s = 0.f;
#pragma unroll
            for (int u = 0; u < 4; u++) {
                float e0 = __expf(acc[t][u][hh * 2 + 0] - rmax[t][hh]);
                float e1 = __expf(acc[t][u][hh * 2 + 1] - rmax[t][hh]);
                acc[t][u][hh * 2 + 0] = e0;
                acc[t][u][hh * 2 + 1] = e1;
                s += e0 + e1;
            }
            s += __shfl_xor_sync(0xffffffffu, s, 1);
            s += __shfl_xor_sync(0xffffffffu, s, 2);
            rsum[t][hh] = s;
        }
    if (qcol == 0) {
#pragma unroll
        for (int t = 0; t < 4; t++)
#pragma unroll
            for (int hh = 0; hh < 2; hh++) {
                int row = wm * 64 + t * 16 + hh * 8 + qrow;
                red[row * 8 + wn] = rsum[t][hh];
            }
    }
    __syncthreads();
#pragma unroll
    for (int t = 0; t < 4; t++)
#pragma unroll
        for (int hh = 0; hh < 2; hh++) {
            int row = wm * 64 + t * 16 + hh * 8 + qrow;
            float s = red[row * 8 + 0];
#pragma unroll
            for (int w = 1; w < 8; w++) s += red[row * 8 + w];
            rsum[t][hh] = 1.f / s;
        }

    // write rounded probabilities
#pragma unroll
    for (int t = 0; t < 4; t++) {
        int r0 = row0 + wm * 64 + t * 16 + qrow;
#pragma unroll
        for (int u = 0; u < 4; u++) {
            int n = wn * 32 + u * 8 + qcol * 2;
            float2 v0, v1;
            v0.x = roundtf(acc[t][u][0] * rsum[t][0]);
            v0.y = roundtf(acc[t][u][1] * rsum[t][0]);
            v1.x = roundtf(acc[t][u][2] * rsum[t][1]);
            v1.y = roundtf(acc[t][u][3] * rsum[t][1]);
            *(float2*)(C + (long)r0 * N1 + n)       = v0;
            *(float2*)(C + (long)(r0 + 8) * N1 + n) = v1;
        }
    }
}

// ---------------- tf32 round-copy (weights) ----------------
__global__ void round_copy_kernel(const float* __restrict__ in, float* __restrict__ out, int n)
{
    int i = blockIdx.x * blockDim.x + threadIdx.x;
    if (i < n) out[i] = roundtf(in[i]);
}

// ---------------- patchify + pos-emb (tf32-rounded output) ----------------
__global__ void patch_embed_kernel(const float* __restrict__ X,
                                   const float* __restrict__ pos,
                                   float* __restrict__ P)
{
    int i = blockIdx.x * blockDim.x + threadIdx.x;
    if (i >= ROWS * D1) return;
    int b   = i >> 16;
    int rem = i & 65535;
    int n   = rem >> 8;
    int d   = rem & 255;
    int gy = n >> 4, gx = n & 15;
    int py = d >> 4, px = d & 15;
    int y = gy * 16 + py, x = gx * 16 + px;
    P[i] = roundtf(X[((long)(b * 256 + y)) * 256 + x] + pos[n * 256 + d]);
}

// ---------------- residual add + LayerNorm; writes full enc and rounded enc_r ----------------
__global__ void add_ln_kernel(float* __restrict__ enc, float* __restrict__ encr,
                              const float* __restrict__ res,
                              const float* __restrict__ g, const float* __restrict__ bta)
{
    int row  = blockIdx.x * (blockDim.x >> 5) + (threadIdx.x >> 5);
    if (row >= ROWS) return;
    int lane = threadIdx.x & 31;
    float* pe = enc + (long)row * 256;
    float* pr2 = encr + (long)row * 256;
    const float* pr = res + (long)row * 256;
    float v[8];
    float s = 0.f;
#pragma unroll
    for (int i = 0; i < 8; i++) { v[i] = pe[lane + i * 32] + pr[lane + i * 32]; s += v[i]; }
#pragma unroll
    for (int o = 16; o > 0; o >>= 1) s += __shfl_xor_sync(0xffffffffu, s, o);
    float mu = s * (1.f / 256.f);
    float q = 0.f;
#pragma unroll
    for (int i = 0; i < 8; i++) { float d = v[i] - mu; q += d * d; }
#pragma unroll
    for (int o = 16; o > 0; o >>= 1) q += __shfl_xor_sync(0xffffffffu, q, o);
    float inv = rsqrtf(q * (1.f / 256.f) + LN_EPS);
#pragma unroll
    for (int i = 0; i < 8; i++) {
        int d = lane + i * 32;
        float w = (v[i] - mu) * inv * g[d] + bta[d];
        pe[d] = w;
        pr2[d] = roundtf(w);
    }
}

// ---------------- final resample: unpatch(16) -> patchify(8) ----------------
__global__ void resample_kernel(const float* __restrict__ enc, float* __restrict__ out)
{
    int i = blockIdx.x * blockDim.x + threadIdx.x;
    if (i >= Bb * 1024 * 64) return;
    int b   = i >> 16;
    int rem = i & 65535;
    int n2  = rem >> 6;
    int d2  = rem & 63;
    int gy2 = n2 >> 5, gx2 = n2 & 31;
    int py2 = d2 >> 3, px2 = d2 & 7;
    int y = gy2 * 8 + py2, x = gx2 * 8 + px2;
    int n1 = (y >> 4) * 16 + (x >> 4);
    int d1 = (y & 15) * 16 + (x & 15);
    out[i] = enc[((long)(b * 256 + n1)) * 256 + d1];
}

extern "C" void kernel_launch(void* const* d_in, const int* in_sizes, int n_in,
                              void* d_out, int out_size)
{
    (void)in_sizes; (void)n_in; (void)out_size;
    const float* X    = (const float*)d_in[0];
    const float* pos  = (const float*)d_in[1];
    const float* W_in = (const float*)d_in[2];
    const float* b_in = (const float*)d_in[3];
    const float* Wq   = (const float*)d_in[4];
    const float* bq   = (const float*)d_in[5];
    const float* Wk   = (const float*)d_in[6];
    const float* bk   = (const float*)d_in[7];
    const float* Wv   = (const float*)d_in[8];
    const float* bv   = (const float*)d_in[9];
    const float* Wo   = (const float*)d_in[10];
    const float* bo   = (const float*)d_in[11];
    const float* ln1g = (const float*)d_in[12];
    const float* ln1b = (const float*)d_in[13];
    const float* ln2g = (const float*)d_in[14];
    const float* ln2b = (const float*)d_in[15];
    const float* W1   = (const float*)d_in[16];
    const float* b1   = (const float*)d_in[17];
    const float* W2   = (const float*)d_in[18];
    const float* b2   = (const float*)d_in[19];
    float* out = (float*)d_out;

    float *patch, *enc, *encr, *q, *k, *v, *attn, *o, *a, *f1;
    float *wrin, *wrq, *wrk, *wrv, *wro, *wr1, *wr2;
    cudaGetSymbolAddress((void**)&patch, g_patch);
    cudaGetSymbolAddress((void**)&enc,   g_enc);
    cudaGetSymbolAddress((void**)&encr,  g_encr);
    cudaGetSymbolAddress((void**)&q,     g_q);
    cudaGetSymbolAddress((void**)&k,     g_k);
    cudaGetSymbolAddress((void**)&v,     g_v);
    cudaGetSymbolAddress((void**)&attn,  g_attn);
    cudaGetSymbolAddress((void**)&o,     g_o);
    cudaGetSymbolAddress((void**)&a,     g_a);
    cudaGetSymbolAddress((void**)&f1,    g_f1);
    cudaGetSymbolAddress((void**)&wrin,  g_wr_in);
    cudaGetSymbolAddress((void**)&wrq,   g_wr_q);
    cudaGetSymbolAddress((void**)&wrk,   g_wr_k);
    cudaGetSymbolAddress((void**)&wrv,   g_wr_v);
    cudaGetSymbolAddress((void**)&wro,   g_wr_o);
    cudaGetSymbolAddress((void**)&wr1,   g_wr_1);
    cudaGetSymbolAddress((void**)&wr2,   g_wr_2);

    cudaFuncSetAttribute(mma_gemm_kernel<false, false, 0>, cudaFuncAttributeMaxDynamicSharedMemorySize, SMEM_GEMM);
    cudaFuncSetAttribute(mma_gemm_kernel<false, false, 1>, cudaFuncAttributeMaxDynamicSharedMemorySize, SMEM_GEMM);
    cudaFuncSetAttribute(mma_gemm_kernel<false, false, 2>, cudaFuncAttributeMaxDynamicSharedMemorySize, SMEM_GEMM);
    cudaFuncSetAttribute(mma_gemm_kernel<false, true,  0>, cudaFuncAttributeMaxDynamicSharedMemorySize, SMEM_GEMM);
    cudaFuncSetAttribute(mma_gemm_kernel<false, true,  1>, cudaFuncAttributeMaxDynamicSharedMemorySize, SMEM_GEMM);
    cudaFuncSetAttribute(qk_softmax_kernel, cudaFuncAttributeMaxDynamicSharedMemorySize, SMEM_QS);

    const float scale = 1.0f / 16.0f;   // 1/sqrt(KD=256)

    // ---- pre-round all weights to tf32 (numerics-identical to per-consume cvt) ----
    round_copy_kernel<<<(D1 * D1 + 255) / 256, 256>>>(W_in, wrin, D1 * D1);
    round_copy_kernel<<<(LAY * D1 * QC + 255) / 256, 256>>>(Wq, wrq, LAY * D1 * QC);
    round_copy_kernel<<<(LAY * D1 * QC + 255) / 256, 256>>>(Wk, wrk, LAY * D1 * QC);
    round_copy_kernel<<<(LAY * D1 * QC + 255) / 256, 256>>>(Wv, wrv, LAY * D1 * QC);
    round_copy_kernel<<<(LAY * QC * D1 + 255) / 256, 256>>>(Wo, wro, LAY * QC * D1);
    round_copy_kernel<<<(LAY * D1 * HID + 255) / 256, 256>>>(W1, wr1, LAY * D1 * HID);
    round_copy_kernel<<<(LAY * HID * D1 + 255) / 256, 256>>>(W2, wr2, LAY * HID * D1);

    patch_embed_kernel<<<(ROWS * D1 + 255) / 256, 256>>>(X, pos, patch);

    // enc = patch @ W_in + b_in  (dual: full enc + rounded encr)
    mma_gemm_kernel<false, false, 2><<<dim3(D1 / BN, ROWS / BM, 1), 256, SMEM_GEMM>>>(
        patch, wrin, b_in, enc, encr, D1, D1, D1, D1, 0, 0, 0, 0, 0, 0, 1, 1.f);

    for (int l = 0; l < LAY; l++) {
        const float* wq_l = wrq + (long)l * D1 * QC;
        const float* wk_l = wrk + (long)l * D1 * QC;
        const float* wv_l = wrv + (long)l * D1 * QC;
        const float* wo_l = wro + (long)l * QC * D1;
        const float* w1_l = wr1 + (long)l * D1 * HID;
        const float* w2_l = wr2 + (long)l * HID * D1;

        mma_gemm_kernel<false, false, 1><<<dim3(QC / BN, ROWS / BM, 1), 256, SMEM_GEMM>>>(
            encr, wq_l, bq + (long)l * QC, q, nullptr, D1, D1, QC, QC, 0, 0, 0, 0, 0, 0, 1, 1.f);
        mma_gemm_kernel<false, false, 1><<<dim3(QC / BN, ROWS / BM, 1), 256, SMEM_GEMM>>>(
            encr, wk_l, bk + (long)l * QC, k, nullptr, D1, D1, QC, QC, 0, 0, 0, 0, 0, 0, 1, 1.f);
        mma_gemm_kernel<false, false, 1><<<dim3(QC / BN, ROWS / BM, 1), 256, SMEM_GEMM>>>(
            encr, wv_l, bv + (long)l * QC, v, nullptr, D1, D1, QC, QC, 0, 0, 0, 0, 0, 0, 1, 1.f);

        // attn = softmax(scale * Q K^T)  — fused GEMM + row softmax, 512 threads
        qk_softmax_kernel<<<dim3(1, N1 / BM, Bb * NH), 512, SMEM_QS>>>(q, k, attn, scale);

        // o = attn @ V  (rounded; consumed only by Wo GEMM)
        mma_gemm_kernel<false, false, 1><<<dim3(KD / BN, N1 / BM, Bb * NH), 256, SMEM_GEMM>>>(
            attn, v, nullptr, o, nullptr, N1, N1, QC, QC,
            (long)NH * N1 * N1, (long)N1 * N1,
            (long)N1 * QC, KD,
            (long)N1 * QC, KD, NH, 1.f);

        // a = o @ Wo + bo  (full; consumed by add_ln)
        mma_gemm_kernel<false, false, 0><<<dim3(D1 / BN, ROWS / BM, 1), 256, SMEM_GEMM>>>(
            o, wo_l, bo + (long)l * D1, a, nullptr, QC, QC, D1, D1, 0, 0, 0, 0, 0, 0, 1, 1.f);

        add_ln_kernel<<<ROWS / 8, 256>>>(enc, encr, a, ln1g + (long)l * D1, ln1b + (long)l * D1);

        mma_gemm_kernel<false, true, 1><<<dim3(HID / BN, ROWS / BM, 1), 256, SMEM_GEMM>>>(
            encr, w1_l, b1 + (long)l * HID, f1, nullptr, D1, D1, HID, HID, 0, 0, 0, 0, 0, 0, 1, 1.f);
        mma_gemm_kernel<false, true, 0><<<dim3(D1 / BN, ROWS / BM, 1), 256, SMEM_GEMM>>>(
            f1, w2_l, b2 + (long)l * D1, a, nullptr, HID, HID, D1, D1, 0, 0, 0, 0, 0, 0, 1, 1.f);

        add_ln_kernel<<<ROWS / 8, 256>>>(enc, encr, a, ln2g + (long)l * D1, ln2b + (long)l * D1);
    }

    resample_kernel<<<(Bb * 1024 * 64 + 255) / 256, 256>>>(enc, out);
}

// round 14
// speedup vs baseline: 1.0141x; 1.0141x over previous
#include <cuda_runtime.h>
#include <math.h>
#include <stdint.h>

// ---------------- problem constants ----------------
constexpr int Bb   = 32;
constexpr int N1   = 256;
constexpr int D1   = 256;
constexpr int NH   = 8;
constexpr int KD   = 256;
constexpr int HID  = 1024;
constexpr int LAY  = 8;
constexpr int ROWS = Bb * N1;      // 8192
constexpr int QC   = NH * KD;      // 2048
constexpr float LN_EPS = 1e-3f;

// ---------------- scratch (static device memory; no allocation) ----------------
__device__ float g_patch[ROWS * D1];
__device__ float g_enc  [ROWS * D1];
__device__ float g_encr [ROWS * D1];         // tf32-rounded copy of enc (GEMM A operand)
__device__ float g_q    [ROWS * QC];
__device__ float g_k    [ROWS * QC];
__device__ float g_v    [ROWS * QC];
__device__ float g_attn [Bb * NH * N1 * N1];
__device__ float g_o    [ROWS * QC];
__device__ float g_a    [ROWS * D1];
__device__ float g_f1   [ROWS * HID];
// tf32-rounded weights (refreshed every call)
__device__ float g_wr_in[D1 * D1];
__device__ float g_wr_q [LAY * D1 * QC];
__device__ float g_wr_k [LAY * D1 * QC];
__device__ float g_wr_v [LAY * D1 * QC];
__device__ float g_wr_o [LAY * QC * D1];
__device__ float g_wr_1 [LAY * D1 * HID];
__device__ float g_wr_2 [LAY * HID * D1];

// ---------------- helpers ----------------
__device__ __forceinline__ float gelu_exact(float x) {
    return 0.5f * x * (1.0f + erff(x * 0.7071067811865476f));
}
__device__ __forceinline__ uint32_t f2tf32(float x) {
    uint32_t r;
    asm("cvt.rna.tf32.f32 %0, %1;" : "=r"(r) : "f"(x));
    return r;
}
__device__ __forceinline__ float roundtf(float x) {
    return __uint_as_float(f2tf32(x));
}
__device__ __forceinline__ float4 roundtf4(float4 v) {
    float4 w;
    w.x = roundtf(v.x); w.y = roundtf(v.y);
    w.z = roundtf(v.z); w.w = roundtf(v.w);
    return w;
}
__device__ __forceinline__ void mma_tf32(float c[4], const uint32_t a[4], const uint32_t b[2]) {
    asm volatile(
        "mma.sync.aligned.m16n8k8.row.col.f32.tf32.tf32.f32 "
        "{%0,%1,%2,%3}, {%4,%5,%6,%7}, {%8,%9}, {%0,%1,%2,%3};\n"
        : "+f"(c[0]), "+f"(c[1]), "+f"(c[2]), "+f"(c[3])
        : "r"(a[0]), "r"(a[1]), "r"(a[2]), "r"(a[3]),
          "r"(b[0]), "r"(b[1]));
}
__device__ __forceinline__ void cp_async16(uint32_t dst_smem, const void* src) {
    asm volatile("cp.async.cg.shared.global [%0], [%1], 16;" :: "r"(dst_smem), "l"(src));
}
__device__ __forceinline__ void cp_commit() {
    asm volatile("cp.async.commit_group;" ::: "memory");
}
template<int N>
__device__ __forceinline__ void cp_wait() {
    asm volatile("cp.async.wait_group %0;" :: "n"(N) : "memory");
}

// ---------------- TF32 tensor-core GEMM: inputs pre-rounded, BK=32, cp.async x2 ----------------
// C[z] = act( alpha * A[z] @ op(B[z]) + bias ); all A/B elements already tf32-rounded.
// A: [M,K] row-major.  NN: B [K,N];  NT: B [N,K] (computes A.B^T)
// Block 128x128x32, 8 warps (2m x 4n), warp tile 64x32, mma m16n8k8.
// OMODE: 0 = store full fp32; 1 = store tf32-rounded; 2 = dual (C full, Cr rounded)
#define BM 128
#define BN 128
#define BK 32
#define AS_LD 36      // [m][k] stride 36 floats: bank = 4*qrow+qcol, conflict-free; 16B-aligned
#define BS_LD 136     // NN [k][n] stride 136: bank = 8*qcol+qrow (+8u), conflict-free
#define A_STG 4608    // 128*36 floats per A stage
#define B_STG 4608    // max(32*136=4352, 128*36=4608) floats per B stage
#define SMEM_GEMM ((2 * A_STG + 2 * B_STG) * 4)   // 73728 bytes

template<bool TRANS_B, bool GELU, int OMODE>
__global__ __launch_bounds__(256, 2)
void mma_gemm_kernel(const float* __restrict__ A, const float* __restrict__ B,
                     const float* __restrict__ bias, float* __restrict__ C,
                     float* __restrict__ Cr,
                     int K, int lda, int ldb, int ldc,
                     long sA1, long sA2, long sB1, long sB2, long sC1, long sC2,
                     int nb2, float alpha)
{
    extern __shared__ float smem[];
    const int z  = blockIdx.z;
    const int z1 = z / nb2, z2 = z - z1 * nb2;
    A += (long)z1 * sA1 + (long)z2 * sA2;
    B += (long)z1 * sB1 + (long)z2 * sB2;
    C += (long)z1 * sC1 + (long)z2 * sC2;
    if (OMODE == 2) Cr += (long)z1 * sC1 + (long)z2 * sC2;

    const int tid  = threadIdx.x;
    const int lane = tid & 31;
    const int wid  = tid >> 5;
    const int wm   = wid >> 2;           // 0..1
    const int wn   = wid & 3;            // 0..3
    const int row0 = blockIdx.y * BM;
    const int col0 = blockIdx.x * BN;

    const int a_row = tid >> 3;          // 0..31
    const int a_col = (tid & 7) << 2;    // 0,4,...,28
    const int b_row = tid >> 5;          // 0..7
    const int b_col = (tid & 31) << 2;   // 0..124

    const int qrow = lane >> 2;          // 0..7
    const int qcol = lane & 3;           // 0..3

    const uint32_t sbase = (uint32_t)__cvta_generic_to_shared(smem);
    const uint32_t offA[2] = {0u, A_STG};
    const uint32_t offB[2] = {2u * A_STG, 2u * A_STG + B_STG};

    float acc[4][4][4];
#pragma unroll
    for (int t = 0; t < 4; t++)
#pragma unroll
        for (int u = 0; u < 4; u++)
#pragma unroll
            for (int r = 0; r < 4; r++) acc[t][u][r] = 0.f;

    const int steps = K >> 5;

    auto fill = [&](int buf, int k0) {
#pragma unroll
        for (int r = 0; r < 4; r++) {
            int m = a_row + r * 32;
            cp_async16(sbase + (offA[buf] + (uint32_t)(m * AS_LD + a_col)) * 4,
                       A + (long)(row0 + m) * lda + k0 + a_col);
        }
        if (!TRANS_B) {
#pragma unroll
            for (int r = 0; r < 4; r++) {
                int kk = b_row + r * 8;
                cp_async16(sbase + (offB[buf] + (uint32_t)(kk * BS_LD + b_col)) * 4,
                           B + (long)(k0 + kk) * ldb + col0 + b_col);
            }
        } else {
#pragma unroll
            for (int r = 0; r < 4; r++) {
                int n = a_row + r * 32;
                cp_async16(sbase + (offB[buf] + (uint32_t)(n * AS_LD + a_col)) * 4,
                           B + (long)(col0 + n) * ldb + k0 + a_col);
            }
        }
    };

    fill(0, 0);     cp_commit();
    fill(1, BK);    cp_commit();

    for (int s = 0; s < steps; s++) {
        if (s + 1 < steps) cp_wait<1>(); else cp_wait<0>();
        __syncthreads();
        const float* Ab   = smem + offA[s & 1];
        const float* Bbuf = smem + offB[s & 1];

#pragma unroll
        for (int ks = 0; ks < BK; ks += 8) {
            uint32_t afrag[4][4];
#pragma unroll
            for (int t = 0; t < 4; t++) {
                int mb = wm * 64 + t * 16;
                afrag[t][0] = __float_as_uint(Ab[(mb + qrow)     * AS_LD + ks + qcol    ]);
                afrag[t][1] = __float_as_uint(Ab[(mb + qrow + 8) * AS_LD + ks + qcol    ]);
                afrag[t][2] = __float_as_uint(Ab[(mb + qrow)     * AS_LD + ks + qcol + 4]);
                afrag[t][3] = __float_as_uint(Ab[(mb + qrow + 8) * AS_LD + ks + qcol + 4]);
            }
            uint32_t bfrag[4][2];
#pragma unroll
            for (int u = 0; u < 4; u++) {
                int nb = wn * 32 + u * 8;
                if (!TRANS_B) {
                    bfrag[u][0] = __float_as_uint(Bbuf[(ks + qcol)     * BS_LD + nb + qrow]);
                    bfrag[u][1] = __float_as_uint(Bbuf[(ks + qcol + 4) * BS_LD + nb + qrow]);
                } else {
                    bfrag[u][0] = __float_as_uint(Bbuf[(nb + qrow) * AS_LD + ks + qcol    ]);
                    bfrag[u][1] = __float_as_uint(Bbuf[(nb + qrow) * AS_LD + ks + qcol + 4]);
                }
            }
#pragma unroll
            for (int t = 0; t < 4; t++)
#pragma unroll
                for (int u = 0; u < 4; u++)
                    mma_tf32(acc[t][u], afrag[t], bfrag[u]);
        }
        __syncthreads();
        if (s + 2 < steps) { fill(s & 1, (s + 2) << 5); cp_commit(); }
    }

#pragma unroll
    for (int t = 0; t < 4; t++) {
        int r0 = row0 + wm * 64 + t * 16 + qrow;
#pragma unroll
        for (int u = 0; u < 4; u++) {
            int n = col0 + wn * 32 + u * 8 + qcol * 2;
            float bx = bias ? bias[n + 0] : 0.f;
            float by = bias ? bias[n + 1] : 0.f;
            float2 v0, v1;
            v0.x = fmaf(acc[t][u][0], alpha, bx);
            v0.y = fmaf(acc[t][u][1], alpha, by);
            v1.x = fmaf(acc[t][u][2], alpha, bx);
            v1.y = fmaf(acc[t][u][3], alpha, by);
            if (GELU) {
                v0.x = gelu_exact(v0.x); v0.y = gelu_exact(v0.y);
                v1.x = gelu_exact(v1.x); v1.y = gelu_exact(v1.y);
            }
            if (OMODE == 1) {
                v0.x = roundtf(v0.x); v0.y = roundtf(v0.y);
                v1.x = roundtf(v1.x); v1.y = roundtf(v1.y);
            }
            *(float2*)(C + (long)r0 * ldc + n)       = v0;
            *(float2*)(C + (long)(r0 + 8) * ldc + n) = v1;
            if (OMODE == 2) {
                float2 w0, w1;
                w0.x = roundtf(v0.x); w0.y = roundtf(v0.y);
                w1.x = roundtf(v1.x); w1.y = roundtf(v1.y);
                *(float2*)(Cr + (long)r0 * ldc + n)       = w0;
                *(float2*)(Cr + (long)(r0 + 8) * ldc + n) = w1;
            }
        }
    }
}

// ---------------- fused tf32 round-copy of ALL weights (single launch, float4) ----------------
__global__ void round_copy_all_kernel(
    const float* __restrict__ W_in, float* __restrict__ wrin,
    const float* __restrict__ Wq,   float* __restrict__ wrq,
    const float* __restrict__ Wk,   float* __restrict__ wrk,
    const float* __restrict__ Wv,   float* __restrict__ wrv,
    const float* __restrict__ Wo,   float* __restrict__ wro,
    const float* __restrict__ W1,   float* __restrict__ wr1,
    const float* __restrict__ W2,   float* __restrict__ wr2)
{
    // sizes in float4 units
    constexpr long N_IN = (long)D1 * D1 / 4;           // 16384
    constexpr long N_P  = (long)LAY * D1 * QC / 4;     // 1048576 (q,k,v,o each)
    constexpr long N_F  = (long)LAY * D1 * HID / 4;    // 524288 (w1,w2 each)
    constexpr long B0 = N_IN;
    constexpr long B1 = B0 + N_P;
    constexpr long B2 = B1 + N_P;
    constexpr long B3 = B2 + N_P;
    constexpr long B4 = B3 + N_P;
    constexpr long B5 = B4 + N_F;
    constexpr long B6 = B5 + N_F;   // total

    long i = (long)blockIdx.x * blockDim.x + threadIdx.x;
    if (i >= B6) return;
    const float4* src; float4* dst; long j;
    if      (i < B0) { src = (const float4*)W_in; dst = (float4*)wrin; j = i; }
    else if (i < B1) { src = (const float4*)Wq;   dst = (float4*)wrq;  j = i - B0; }
    else if (i < B2) { src = (const float4*)Wk;   dst = (float4*)wrk;  j = i - B1; }
    else if (i < B3) { src = (const float4*)Wv;   dst = (float4*)wrv;  j = i - B2; }
    else if (i < B4) { src = (const float4*)Wo;   dst = (float4*)wro;  j = i - B3; }
    else if (i < B5) { src = (const float4*)W1;   dst = (float4*)wr1;  j = i - B4; }
    else             { src = (const float4*)W2;   dst = (float4*)wr2;  j = i - B5; }
    dst[j] = roundtf4(src[j]);
}
constexpr long RCA_TOTAL4 = (long)D1 * D1 / 4 + 4L * LAY * D1 * QC / 4 + 2L * LAY * D1 * HID / 4;

// ---------------- patchify + pos-emb (tf32-rounded output) ----------------
__global__ void patch_embed_kernel(const float* __restrict__ X,
                                   const float* __restrict__ pos,
                                   float* __restrict__ P)
{
    int i = blockIdx.x * blockDim.x + threadIdx.x;
    if (i >= ROWS * D1) return;
    int b   = i >> 16;
    int rem = i & 65535;
    int n   = rem >> 8;
    int d   = rem & 255;
    int gy = n >> 4, gx = n & 15;
    int py = d >> 4, px = d & 15;
    int y = gy * 16 + py, x = gx * 16 + px;
    P[i] = roundtf(X[((long)(b * 256 + y)) * 256 + x] + pos[n * 256 + d]);
}

// ---------------- softmax over rows of 256 (warp per row, float4 I/O) ----------------
__global__ void softmax_kernel(float* __restrict__ A, int nrows)
{
    int row  = blockIdx.x * (blockDim.x >> 5) + (threadIdx.x >> 5);
    if (row >= nrows) return;
    int lane = threadIdx.x & 31;
    float4* p = (float4*)(A + (long)row * 256) + lane * 2;
    float4 a = p[0], b = p[1];
    float v[8] = {a.x, a.y, a.z, a.w, b.x, b.y, b.z, b.w};
    float mx = v[0];
#pragma unroll
    for (int i = 1; i < 8; i++) mx = fmaxf(mx, v[i]);
#pragma unroll
    for (int o = 16; o > 0; o >>= 1) mx = fmaxf(mx, __shfl_xor_sync(0xffffffffu, mx, o));
    float s = 0.f;
#pragma unroll
    for (int i = 0; i < 8; i++) { v[i] = __expf(v[i] - mx); s += v[i]; }
#pragma unroll
    for (int o = 16; o > 0; o >>= 1) s += __shfl_xor_sync(0xffffffffu, s, o);
    float r = 1.f / s;
    float4 oa, ob;
    oa.x = roundtf(v[0] * r); oa.y = roundtf(v[1] * r);
    oa.z = roundtf(v[2] * r); oa.w = roundtf(v[3] * r);
    ob.x = roundtf(v[4] * r); ob.y = roundtf(v[5] * r);
    ob.z = roundtf(v[6] * r); ob.w = roundtf(v[7] * r);
    p[0] = oa; p[1] = ob;
}

// ---------------- residual add + LayerNorm (warp per row, float4 I/O); dual write ----------------
__global__ void add_ln_kernel(float* __restrict__ enc, float* __restrict__ encr,
                              const float* __restrict__ res,
                              const float* __restrict__ g, const float* __restrict__ bta)
{
    int row  = blockIdx.x * (blockDim.x >> 5) + (threadIdx.x >> 5);
    if (row >= ROWS) return;
    int lane = threadIdx.x & 31;
    float4* pe  = (float4*)(enc  + (long)row * 256) + lane * 2;
    float4* pr2 = (float4*)(encr + (long)row * 256) + lane * 2;
    const float4* pr = (const float4*)(res + (long)row * 256) + lane * 2;
    const float4* pg = (const float4*)g   + lane * 2;
    const float4* pb = (const float4*)bta + lane * 2;

    float4 e0 = pe[0], e1 = pe[1];
    float4 r0 = pr[0], r1 = pr[1];
    float v[8] = {e0.x + r0.x, e0.y + r0.y, e0.z + r0.z, e0.w + r0.w,
                  e1.x + r1.x, e1.y + r1.y, e1.z + r1.z, e1.w + r1.w};
    float s = 0.f;
#pragma unroll
    for (int i = 0; i < 8; i++) s += v[i];
#pragma unroll
    for (int o = 16; o > 0; o >>= 1) s += __shfl_xor_sync(0xffffffffu, s, o);
    float mu = s * (1.f / 256.f);
    float q = 0.f;
#pragma unroll
    for (int i = 0; i < 8; i++) { float d = v[i] - mu; q += d * d; }
#pragma unroll
    for (int o = 16; o > 0; o >>= 1) q += __shfl_xor_sync(0xffffffffu, q, o);
    float inv = rsqrtf(q * (1.f / 256.f) + LN_EPS);

    float4 g0 = pg[0], g1 = pg[1], b0 = pb[0], b1 = pb[1];
    float4 w0, w1;
    w0.x = (v[0] - mu) * inv * g0.x + b0.x;
    w0.y = (v[1] - mu) * inv * g0.y + b0.y;
    w0.z = (v[2] - mu) * inv * g0.z + b0.z;
    w0.w = (v[3] - mu) * inv * g0.w + b0.w;
    w1.x = (v[4] - mu) * inv * g1.x + b1.x;
    w1.y = (v[5] - mu) * inv * g1.y + b1.y;
    w1.z = (v[6] - mu) * inv * g1.z + b1.z;
    w1.w = (v[7] - mu) * inv * g1.w + b1.w;
    pe[0] = w0; pe[1] = w1;
    pr2[0] = roundtf4(w0); pr2[1] = roundtf4(w1);
}

// ---------------- final resample: unpatch(16) -> patchify(8) ----------------
__global__ void resample_kernel(const float* __restrict__ enc, float* __restrict__ out)
{
    int i = blockIdx.x * blockDim.x + threadIdx.x;
    if (i >= Bb * 1024 * 64) return;
    int b   = i >> 16;
    int rem = i & 65535;
    int n2  = rem >> 6;
    int d2  = rem & 63;
    int gy2 = n2 >> 5, gx2 = n2 & 31;
    int py2 = d2 >> 3, px2 = d2 & 7;
    int y = gy2 * 8 + py2, x = gx2 * 8 + px2;
    int n1 = (y >> 4) * 16 + (x >> 4);
    int d1 = (y & 15) * 16 + (x & 15);
    out[i] = enc[((long)(b * 256 + n1)) * 256 + d1];
}

extern "C" void kernel_launch(void* const* d_in, const int* in_sizes, int n_in,
                              void* d_out, int out_size)
{
    (void)in_sizes; (void)n_in; (void)out_size;
    const float* X    = (const float*)d_in[0];
    const float* pos  = (const float*)d_in[1];
    const float* W_in = (const float*)d_in[2];
    const float* b_in = (const float*)d_in[3];
    const float* Wq   = (const float*)d_in[4];
    const float* bq   = (const float*)d_in[5];
    const float* Wk   = (const float*)d_in[6];
    const float* bk   = (const float*)d_in[7];
    const float* Wv   = (const float*)d_in[8];
    const float* bv   = (const float*)d_in[9];
    const float* Wo   = (const float*)d_in[10];
    const float* bo   = (const float*)d_in[11];
    const float* ln1g = (const float*)d_in[12];
    const float* ln1b = (const float*)d_in[13];
    const float* ln2g = (const float*)d_in[14];
    const float* ln2b = (const float*)d_in[15];
    const float* W1   = (const float*)d_in[16];
    const float* b1   = (const float*)d_in[17];
    const float* W2   = (const float*)d_in[18];
    const float* b2   = (const float*)d_in[19];
    float* out = (float*)d_out;

    float *patch, *enc, *encr, *q, *k, *v, *attn, *o, *a, *f1;
    float *wrin, *wrq, *wrk, *wrv, *wro, *wr1, *wr2;
    cudaGetSymbolAddress((void**)&patch, g_patch);
    cudaGetSymbolAddress((void**)&enc,   g_enc);
    cudaGetSymbolAddress((void**)&encr,  g_encr);
    cudaGetSymbolAddress((void**)&q,     g_q);
    cudaGetSymbolAddress((void**)&k,     g_k);
    cudaGetSymbolAddress((void**)&v,     g_v);
    cudaGetSymbolAddress((void**)&attn,  g_attn);
    cudaGetSymbolAddress((void**)&o,     g_o);
    cudaGetSymbolAddress((void**)&a,     g_a);
    cudaGetSymbolAddress((void**)&f1,    g_f1);
    cudaGetSymbolAddress((void**)&wrin,  g_wr_in);
    cudaGetSymbolAddress((void**)&wrq,   g_wr_q);
    cudaGetSymbolAddress((void**)&wrk,   g_wr_k);
    cudaGetSymbolAddress((void**)&wrv,   g_wr_v);
    cudaGetSymbolAddress((void**)&wro,   g_wr_o);
    cudaGetSymbolAddress((void**)&wr1,   g_wr_1);
    cudaGetSymbolAddress((void**)&wr2,   g_wr_2);

    cudaFuncSetAttribute(mma_gemm_kernel<false, false, 0>, cudaFuncAttributeMaxDynamicSharedMemorySize, SMEM_GEMM);
    cudaFuncSetAttribute(mma_gemm_kernel<false, false, 1>, cudaFuncAttributeMaxDynamicSharedMemorySize, SMEM_GEMM);
    cudaFuncSetAttribute(mma_gemm_kernel<false, false, 2>, cudaFuncAttributeMaxDynamicSharedMemorySize, SMEM_GEMM);
    cudaFuncSetAttribute(mma_gemm_kernel<true,  false, 0>, cudaFuncAttributeMaxDynamicSharedMemorySize, SMEM_GEMM);
    cudaFuncSetAttribute(mma_gemm_kernel<false, true,  0>, cudaFuncAttributeMaxDynamicSharedMemorySize, SMEM_GEMM);
    cudaFuncSetAttribute(mma_gemm_kernel<false, true,  1>, cudaFuncAttributeMaxDynamicSharedMemorySize, SMEM_GEMM);

    const float scale = 1.0f / 16.0f;   // 1/sqrt(KD=256)

    // ---- pre-round all weights to tf32 (single launch; numerics-identical) ----
    round_copy_all_kernel<<<(int)((RCA_TOTAL4 + 255) / 256), 256>>>(
        W_in, wrin, Wq, wrq, Wk, wrk, Wv, wrv, Wo, wro, W1, wr1, W2, wr2);

    patch_embed_kernel<<<(ROWS * D1 + 255) / 256, 256>>>(X, pos, patch);

    // enc = patch @ W_in + b_in  (dual: full enc + rounded encr)
    mma_gemm_kernel<false, false, 2><<<dim3(D1 / BN, ROWS / BM, 1), 256, SMEM_GEMM>>>(
        patch, wrin, b_in, enc, encr, D1, D1, D1, D1, 0, 0, 0, 0, 0, 0, 1, 1.f);

    for (int l = 0; l < LAY; l++) {
        const float* wq_l = wrq + (long)l * D1 * QC;
        const float* wk_l = wrk + (long)l * D1 * QC;
        const float* wv_l = wrv + (long)l * D1 * QC;
        const float* wo_l = wro + (long)l * QC * D1;
        const float* w1_l = wr1 + (long)l * D1 * HID;
        const float* w2_l = wr2 + (long)l * HID * D1;

        // q,k,v = encr @ W + b  (rounded outputs; consumed only by GEMMs)
        mma_gemm_kernel<false, false, 1><<<dim3(QC / BN, ROWS / BM, 1), 256, SMEM_GEMM>>>(
            encr, wq_l, bq + (long)l * QC, q, nullptr, D1, D1, QC, QC, 0, 0, 0, 0, 0, 0, 1, 1.f);
        mma_gemm_kernel<false, false, 1><<<dim3(QC / BN, ROWS / BM, 1), 256, SMEM_GEMM>>>(
            encr, wk_l, bk + (long)l * QC, k, nullptr, D1, D1, QC, QC, 0, 0, 0, 0, 0, 0, 1, 1.f);
        mma_gemm_kernel<false, false, 1><<<dim3(QC / BN, ROWS / BM, 1), 256, SMEM_GEMM>>>(
            encr, wv_l, bv + (long)l * QC, v, nullptr, D1, D1, QC, QC, 0, 0, 0, 0, 0, 0, 1, 1.f);

        // logits[b,h,q,n] = scale * Q_bh @ K_bh^T  (full precision for softmax)
        mma_gemm_kernel<true, false, 0><<<dim3(N1 / BN, N1 / BM, Bb * NH), 256, SMEM_GEMM>>>(
            q, k, nullptr, attn, nullptr, KD, QC, QC, N1,
            (long)N1 * QC, KD, (long)N1 * QC, KD,
            (long)NH * N1 * N1, (long)N1 * N1, NH, scale);

        softmax_kernel<<<(Bb * NH * N1) / 8, 256>>>(attn, Bb * NH * N1);

        // o = attn @ V  (rounded; consumed only by Wo GEMM)
        mma_gemm_kernel<false, false, 1><<<dim3(KD / BN, N1 / BM, Bb * NH), 256, SMEM_GEMM>>>(
            attn, v, nullptr, o, nullptr, N1, N1, QC, QC,
            (long)NH * N1 * N1, (long)N1 * N1,
            (long)N1 * QC, KD,
            (long)N1 * QC, KD, NH, 1.f);

        // a = o @ Wo + bo  (full; consumed by add_ln)
        mma_gemm_kernel<false, false, 0><<<dim3(D1 / BN, ROWS / BM, 1), 256, SMEM_GEMM>>>(
            o, wo_l, bo + (long)l * D1, a, nullptr, QC, QC, D1, D1, 0, 0, 0, 0, 0, 0, 1, 1.f);

        add_ln_kernel<<<ROWS / 8, 256>>>(enc, encr, a, ln1g + (long)l * D1, ln1b + (long)l * D1);

        // f1 = gelu(encr @ W1 + b1)  (rounded; consumed by W2 GEMM)
        mma_gemm_kernel<false, true, 1><<<dim3(HID / BN, ROWS / BM, 1), 256, SMEM_GEMM>>>(
            encr, w1_l, b1 + (long)l * HID, f1, nullptr, D1, D1, HID, HID, 0, 0, 0, 0, 0, 0, 1, 1.f);
        // f2 = gelu(f1 @ W2 + b2)  (full; consumed by add_ln)
        mma_gemm_kernel<false, true, 0><<<dim3(D1 / BN, ROWS / BM, 1), 256, SMEM_GEMM>>>(
            f1, w2_l, b2 + (long)l * D1, a, nullptr, HID, HID, D1, D1, 0, 0, 0, 0, 0, 0, 1, 1.f);

        add_ln_kernel<<<ROWS / 8, 256>>>(enc, encr, a, ln2g + (long)l * D1, ln2b + (long)l * D1);
    }

    resample_kernel<<<(Bb * 1024 * 64 + 255) / 256, 256>>>(enc, out);
}

// round 16
// speedup vs baseline: 1.0168x; 1.0027x over previous
#include <cuda_runtime.h>
#include <math.h>
#include <stdint.h>

// ---------------- problem constants ----------------
constexpr int Bb   = 32;
constexpr int N1   = 256;
constexpr int D1   = 256;
constexpr int NH   = 8;
constexpr int KD   = 256;
constexpr int HID  = 1024;
constexpr int LAY  = 8;
constexpr int ROWS = Bb * N1;      // 8192
constexpr int QC   = NH * KD;      // 2048
constexpr int QC3  = 3 * QC;       // 6144
constexpr float LN_EPS = 1e-3f;

// ---------------- scratch (static device memory; no allocation) ----------------
__device__ float g_patch[ROWS * D1];
__device__ float g_enc  [ROWS * D1];
__device__ float g_encr [ROWS * D1];          // tf32-rounded copy of enc (GEMM A operand)
__device__ float g_qkv  [ROWS * QC3];         // fused q|k|v, 192 MB
__device__ float g_attn [Bb * NH * N1 * N1];
__device__ float g_o    [ROWS * QC];
__device__ float g_a    [ROWS * D1];
__device__ float g_f1   [ROWS * HID];
__device__ float g_wop  [2 * ROWS * D1];      // Wo split-K partials
// tf32-rounded weights (refreshed every call)
__device__ float g_wr_in [D1 * D1];
__device__ float g_wr_qkv[LAY * D1 * QC3];    // packed [d][Wq|Wk|Wv]
__device__ float g_wr_o  [LAY * QC * D1];
__device__ float g_wr_1  [LAY * D1 * HID];
__device__ float g_wr_2  [LAY * HID * D1];
__device__ float g_bqkv  [LAY * QC3];         // packed bq|bk|bv

// ---------------- helpers ----------------
__device__ __forceinline__ float gelu_exact(float x) {
    return 0.5f * x * (1.0f + erff(x * 0.7071067811865476f));
}
__device__ __forceinline__ uint32_t f2tf32(float x) {
    uint32_t r;
    asm("cvt.rna.tf32.f32 %0, %1;" : "=r"(r) : "f"(x));
    return r;
}
__device__ __forceinline__ float roundtf(float x) {
    return __uint_as_float(f2tf32(x));
}
__device__ __forceinline__ float4 roundtf4(float4 v) {
    float4 w;
    w.x = roundtf(v.x); w.y = roundtf(v.y);
    w.z = roundtf(v.z); w.w = roundtf(v.w);
    return w;
}
__device__ __forceinline__ void mma_tf32(float c[4], const uint32_t a[4], const uint32_t b[2]) {
    asm volatile(
        "mma.sync.aligned.m16n8k8.row.col.f32.tf32.tf32.f32 "
        "{%0,%1,%2,%3}, {%4,%5,%6,%7}, {%8,%9}, {%0,%1,%2,%3};\n"
        : "+f"(c[0]), "+f"(c[1]), "+f"(c[2]), "+f"(c[3])
        : "r"(a[0]), "r"(a[1]), "r"(a[2]), "r"(a[3]),
          "r"(b[0]), "r"(b[1]));
}
__device__ __forceinline__ void cp_async16(uint32_t dst_smem, const void* src) {
    asm volatile("cp.async.cg.shared.global [%0], [%1], 16;" :: "r"(dst_smem), "l"(src));
}
__device__ __forceinline__ void cp_commit() {
    asm volatile("cp.async.commit_group;" ::: "memory");
}
template<int N>
__device__ __forceinline__ void cp_wait() {
    asm volatile("cp.async.wait_group %0;" :: "n"(N) : "memory");
}

// ---------------- TF32 tensor-core GEMM: inputs pre-rounded, BK=32, cp.async x2 ----------------
// C[z] = act( alpha * A[z] @ op(B[z]) + bias ); all A/B elements already tf32-rounded.
// A: [M,K] row-major.  NN: B [K,N];  NT: B [N,K] (computes A.B^T)
// Block 128x128x32, 8 warps (2m x 4n), warp tile 64x32, mma m16n8k8.
// OMODE: 0 = store full fp32; 1 = store tf32-rounded; 2 = dual (C full, Cr rounded)
#define BM 128
#define BN 128
#define BK 32
#define AS_LD 36
#define BS_LD 136
#define A_STG 4608
#define B_STG 4608
#define SMEM_GEMM ((2 * A_STG + 2 * B_STG) * 4)   // 73728 bytes

template<bool TRANS_B, bool GELU, int OMODE>
__global__ __launch_bounds__(256, 2)
void mma_gemm_kernel(const float* __restrict__ A, const float* __restrict__ B,
                     const float* __restrict__ bias, float* __restrict__ C,
                     float* __restrict__ Cr,
                     int K, int lda, int ldb, int ldc,
                     long sA1, long sA2, long sB1, long sB2, long sC1, long sC2,
                     int nb2, float alpha)
{
    extern __shared__ float smem[];
    const int z  = blockIdx.z;
    const int z1 = z / nb2, z2 = z - z1 * nb2;
    A += (long)z1 * sA1 + (long)z2 * sA2;
    B += (long)z1 * sB1 + (long)z2 * sB2;
    C += (long)z1 * sC1 + (long)z2 * sC2;
    if (OMODE == 2) Cr += (long)z1 * sC1 + (long)z2 * sC2;

    const int tid  = threadIdx.x;
    const int lane = tid & 31;
    const int wid  = tid >> 5;
    const int wm   = wid >> 2;
    const int wn   = wid & 3;
    const int row0 = blockIdx.y * BM;
    const int col0 = blockIdx.x * BN;

    const int a_row = tid >> 3;
    const int a_col = (tid & 7) << 2;
    const int b_row = tid >> 5;
    const int b_col = (tid & 31) << 2;

    const int qrow = lane >> 2;
    const int qcol = lane & 3;

    const uint32_t sbase = (uint32_t)__cvta_generic_to_shared(smem);
    const uint32_t offA[2] = {0u, A_STG};
    const uint32_t offB[2] = {2u * A_STG, 2u * A_STG + B_STG};

    float acc[4][4][4];
#pragma unroll
    for (int t = 0; t < 4; t++)
#pragma unroll
        for (int u = 0; u < 4; u++)
#pragma unroll
            for (int r = 0; r < 4; r++) acc[t][u][r] = 0.f;

    const int steps = K >> 5;

    auto fill = [&](int buf, int k0) {
#pragma unroll
        for (int r = 0; r < 4; r++) {
            int m = a_row + r * 32;
            cp_async16(sbase + (offA[buf] + (uint32_t)(m * AS_LD + a_col)) * 4,
                       A + (long)(row0 + m) * lda + k0 + a_col);
        }
        if (!TRANS_B) {
#pragma unroll
            for (int r = 0; r < 4; r++) {
                int kk = b_row + r * 8;
                cp_async16(sbase + (offB[buf] + (uint32_t)(kk * BS_LD + b_col)) * 4,
                           B + (long)(k0 + kk) * ldb + col0 + b_col);
            }
        } else {
#pragma unroll
            for (int r = 0; r < 4; r++) {
                int n = a_row + r * 32;
                cp_async16(sbase + (offB[buf] + (uint32_t)(n * AS_LD + a_col)) * 4,
                           B + (long)(col0 + n) * ldb + k0 + a_col);
            }
        }
    };

    fill(0, 0);     cp_commit();
    fill(1, BK);    cp_commit();

    for (int s = 0; s < steps; s++) {
        if (s + 1 < steps) cp_wait<1>(); else cp_wait<0>();
        __syncthreads();
        const float* Ab   = smem + offA[s & 1];
        const float* Bbuf = smem + offB[s & 1];

#pragma unroll
        for (int ks = 0; ks < BK; ks += 8) {
            uint32_t afrag[4][4];
#pragma unroll
            for (int t = 0; t < 4; t++) {
                int mb = wm * 64 + t * 16;
                afrag[t][0] = __float_as_uint(Ab[(mb + qrow)     * AS_LD + ks + qcol    ]);
                afrag[t][1] = __float_as_uint(Ab[(mb + qrow + 8) * AS_LD + ks + qcol    ]);
                afrag[t][2] = __float_as_uint(Ab[(mb + qrow)     * AS_LD + ks + qcol + 4]);
                afrag[t][3] = __float_as_uint(Ab[(mb + qrow + 8) * AS_LD + ks + qcol + 4]);
            }
            uint32_t bfrag[4][2];
#pragma unroll
            for (int u = 0; u < 4; u++) {
                int nb = wn * 32 + u * 8;
                if (!TRANS_B) {
                    bfrag[u][0] = __float_as_uint(Bbuf[(ks + qcol)     * BS_LD + nb + qrow]);
                    bfrag[u][1] = __float_as_uint(Bbuf[(ks + qcol + 4) * BS_LD + nb + qrow]);
                } else {
                    bfrag[u][0] = __float_as_uint(Bbuf[(nb + qrow) * AS_LD + ks + qcol    ]);
                    bfrag[u][1] = __float_as_uint(Bbuf[(nb + qrow) * AS_LD + ks + qcol + 4]);
                }
            }
#pragma unroll
            for (int t = 0; t < 4; t++)
#pragma unroll
                for (int u = 0; u < 4; u++)
                    mma_tf32(acc[t][u], afrag[t], bfrag[u]);
        }
        __syncthreads();
        if (s + 2 < steps) { fill(s & 1, (s + 2) << 5); cp_commit(); }
    }

#pragma unroll
    for (int t = 0; t < 4; t++) {
        int r0 = row0 + wm * 64 + t * 16 + qrow;
#pragma unroll
        for (int u = 0; u < 4; u++) {
            int n = col0 + wn * 32 + u * 8 + qcol * 2;
            float bx = bias ? bias[n + 0] : 0.f;
            float by = bias ? bias[n + 1] : 0.f;
            float2 v0, v1;
            v0.x = fmaf(acc[t][u][0], alpha, bx);
            v0.y = fmaf(acc[t][u][1], alpha, by);
            v1.x = fmaf(acc[t][u][2], alpha, bx);
            v1.y = fmaf(acc[t][u][3], alpha, by);
            if (GELU) {
                v0.x = gelu_exact(v0.x); v0.y = gelu_exact(v0.y);
                v1.x = gelu_exact(v1.x); v1.y = gelu_exact(v1.y);
            }
            if (OMODE == 1) {
                v0.x = roundtf(v0.x); v0.y = roundtf(v0.y);
                v1.x = roundtf(v1.x); v1.y = roundtf(v1.y);
            }
            *(float2*)(C + (long)r0 * ldc + n)       = v0;
            *(float2*)(C + (long)(r0 + 8) * ldc + n) = v1;
            if (OMODE == 2) {
                float2 w0, w1;
                w0.x = roundtf(v0.x); w0.y = roundtf(v0.y);
                w1.x = roundtf(v1.x); w1.y = roundtf(v1.y);
                *(float2*)(Cr + (long)r0 * ldc + n)       = w0;
                *(float2*)(Cr + (long)(r0 + 8) * ldc + n) = w1;
            }
        }
    }
}

// ---------------- fused tf32 round-copy of ALL weights; QKV packed interleaved ----------------
__global__ void round_copy_all_kernel(
    const float* __restrict__ W_in, float* __restrict__ wrin,
    const float* __restrict__ Wq,
    const float* __restrict__ Wk,
    const float* __restrict__ Wv,   float* __restrict__ wrqkv,
    const float* __restrict__ Wo,   float* __restrict__ wro,
    const float* __restrict__ W1,   float* __restrict__ wr1,
    const float* __restrict__ W2,   float* __restrict__ wr2)
{
    constexpr long N_IN = (long)D1 * D1 / 4;           // 16384
    constexpr long N_P  = (long)LAY * D1 * QC / 4;     // 1048576 each (q,k,v,o)
    constexpr long N_F  = (long)LAY * D1 * HID / 4;    // 524288 each (w1,w2)
    constexpr long B0 = N_IN;
    constexpr long B1 = B0 + N_P;
    constexpr long B2 = B1 + N_P;
    constexpr long B3 = B2 + N_P;
    constexpr long B4 = B3 + N_P;
    constexpr long B5 = B4 + N_F;
    constexpr long B6 = B5 + N_F;

    constexpr long LDQ4   = QC / 4;          // 512
    constexpr long ROW4   = QC3 / 4;         // 1536
    constexpr long LAYP4  = (long)D1 * QC / 4;   // per-layer float4 count of one projection
    constexpr long LAYQ4  = (long)D1 * QC3 / 4;  // per-layer float4 count of packed qkv

    long i = (long)blockIdx.x * blockDim.x + threadIdx.x;
    if (i >= B6) return;

    if (i < B0) {
        ((float4*)wrin)[i] = roundtf4(((const float4*)W_in)[i]);
    } else if (i < B4) {
        long seg = (i - B0) / N_P;           // 0=q,1=k,2=v,3=o
        long j   = (i - B0) - seg * N_P;
        if (seg == 3) {
            ((float4*)wro)[j] = roundtf4(((const float4*)Wo)[j]);
        } else {
            const float4* src = (seg == 0) ? (const float4*)Wq
                              : (seg == 1) ? (const float4*)Wk : (const float4*)Wv;
            long l   = j / LAYP4;
            long rem = j - l * LAYP4;
            long d   = rem / LDQ4;
            long c4  = rem - d * LDQ4;
            ((float4*)wrqkv)[l * LAYQ4 + d * ROW4 + seg * LDQ4 + c4] = roundtf4(src[j]);
        }
    } else if (i < B5) {
        long j = i - B4;
        ((float4*)wr1)[j] = roundtf4(((const float4*)W1)[j]);
    } else {
        long j = i - B5;
        ((float4*)wr2)[j] = roundtf4(((const float4*)W2)[j]);
    }
}
constexpr long RCA_TOTAL4 = (long)D1 * D1 / 4 + 4L * LAY * D1 * QC / 4 + 2L * LAY * D1 * HID / 4;

// ---------------- pack q/k/v biases -> [LAY][6144] ----------------
__global__ void pack_bias_kernel(const float* __restrict__ bq, const float* __restrict__ bk,
                                 const float* __restrict__ bv, float* __restrict__ bqkv)
{
    int i = blockIdx.x * blockDim.x + threadIdx.x;
    if (i >= LAY * QC3) return;
    int l = i / QC3, c = i - l * QC3;
    float v;
    if (c < QC)          v = bq[l * QC + c];
    else if (c < 2 * QC) v = bk[l * QC + c - QC];
    else                 v = bv[l * QC + c - 2 * QC];
    bqkv[i] = v;
}

// ---------------- split-K reduce: out = p0 + p1 + bias (float4) ----------------
__global__ void splitk_reduce_kernel(const float* __restrict__ p, const float* __restrict__ bias,
                                     float* __restrict__ outp)
{
    int i = blockIdx.x * blockDim.x + threadIdx.x;      // float4 index over ROWS*D1/4
    if (i >= ROWS * D1 / 4) return;
    const float4* p0 = (const float4*)p;
    const float4* p1 = (const float4*)(p + (long)ROWS * D1);
    float4 a = p0[i], b = p1[i];
    float4 bb = ((const float4*)bias)[i & (D1 / 4 - 1)];
    float4 w;
    w.x = a.x + b.x + bb.x;
    w.y = a.y + b.y + bb.y;
    w.z = a.z + b.z + bb.z;
    w.w = a.w + b.w + bb.w;
    ((float4*)outp)[i] = w;
}

// ---------------- patchify + pos-emb (tf32-rounded output) ----------------
__global__ void patch_embed_kernel(const float* __restrict__ X,
                                   const float* __restrict__ pos,
                                   float* __restrict__ P)
{
    int i = blockIdx.x * blockDim.x + threadIdx.x;
    if (i >= ROWS * D1) return;
    int b   = i >> 16;
    int rem = i & 65535;
    int n   = rem >> 8;
    int d   = rem & 255;
    int gy = n >> 4, gx = n & 15;
    int py = d >> 4, px = d & 15;
    int y = gy * 16 + py, x = gx * 16 + px;
    P[i] = roundtf(X[((long)(b * 256 + y)) * 256 + x] + pos[n * 256 + d]);
}

// ---------------- softmax over rows of 256 (warp per row, float4 I/O) ----------------
__global__ void softmax_kernel(float* __restrict__ A, int nrows)
{
    int row  = blockIdx.x * (blockDim.x >> 5) + (threadIdx.x >> 5);
    if (row >= nrows) return;
    int lane = threadIdx.x & 31;
    float4* p = (float4*)(A + (long)row * 256) + lane * 2;
    float4 a = p[0], b = p[1];
    float v[8] = {a.x, a.y, a.z, a.w, b.x, b.y, b.z, b.w};
    float mx = v[0];
#pragma unroll
    for (int i = 1; i < 8; i++) mx = fmaxf(mx, v[i]);
#pragma unroll
    for (int o = 16; o > 0; o >>= 1) mx = fmaxf(mx, __shfl_xor_sync(0xffffffffu, mx, o));
    float s = 0.f;
#pragma unroll
    for (int i = 0; i < 8; i++) { v[i] = __expf(v[i] - mx); s += v[i]; }
#pragma unroll
    for (int o = 16; o > 0; o >>= 1) s += __shfl_xor_sync(0xffffffffu, s, o);
    float r = 1.f / s;
    float4 oa, ob;
    oa.x = roundtf(v[0] * r); oa.y = roundtf(v[1] * r);
    oa.z = roundtf(v[2] * r); oa.w = roundtf(v[3] * r);
    ob.x = roundtf(v[4] * r); ob.y = roundtf(v[5] * r);
    ob.z = roundtf(v[6] * r); ob.w = roundtf(v[7] * r);
    p[0] = oa; p[1] = ob;
}

// ---------------- residual add + LayerNorm (warp per row, float4 I/O); dual write ----------------
__global__ void add_ln_kernel(float* __restrict__ enc, float* __restrict__ encr,
                              const float* __restrict__ res,
                              const float* __restrict__ g, const float* __restrict__ bta)
{
    int row  = blockIdx.x * (blockDim.x >> 5) + (threadIdx.x >> 5);
    if (row >= ROWS) return;
    int lane = threadIdx.x & 31;
    float4* pe  = (float4*)(enc  + (long)row * 256) + lane * 2;
    float4* pr2 = (float4*)(encr + (long)row * 256) + lane * 2;
    const float4* pr = (const float4*)(res + (long)row * 256) + lane * 2;
    const float4* pg = (const float4*)g   + lane * 2;
    const float4* pb = (const float4*)bta + lane * 2;

    float4 e0 = pe[0], e1 = pe[1];
    float4 r0 = pr[0], r1 = pr[1];
    float v[8] = {e0.x + r0.x, e0.y + r0.y, e0.z + r0.z, e0.w + r0.w,
                  e1.x + r1.x, e1.y + r1.y, e1.z + r1.z, e1.w + r1.w};
    float s = 0.f;
#pragma unroll
    for (int i = 0; i < 8; i++) s += v[i];
#pragma unroll
    for (int o = 16; o > 0; o >>= 1) s += __shfl_xor_sync(0xffffffffu, s, o);
    float mu = s * (1.f / 256.f);
    float q = 0.f;
#pragma unroll
    for (int i = 0; i < 8; i++) { float d = v[i] - mu; q += d * d; }
#pragma unroll
    for (int o = 16; o > 0; o >>= 1) q += __shfl_xor_sync(0xffffffffu, q, o);
    float inv = rsqrtf(q * (1.f / 256.f) + LN_EPS);

    float4 g0 = pg[0], g1 = pg[1], b0 = pb[0], b1 = pb[1];
    float4 w0, w1;
    w0.x = (v[0] - mu) * inv * g0.x + b0.x;
    w0.y = (v[1] - mu) * inv * g0.y + b0.y;
    w0.z = (v[2] - mu) * inv * g0.z + b0.z;
    w0.w = (v[3] - mu) * inv * g0.w + b0.w;
    w1.x = (v[4] - mu) * inv * g1.x + b1.x;
    w1.y = (v[5] - mu) * inv * g1.y + b1.y;
    w1.z = (v[6] - mu) * inv * g1.z + b1.z;
    w1.w = (v[7] - mu) * inv * g1.w + b1.w;
    pe[0] = w0; pe[1] = w1;
    pr2[0] = roundtf4(w0); pr2[1] = roundtf4(w1);
}

// ---------------- final resample: unpatch(16) -> patchify(8) ----------------
__global__ void resample_kernel(const float* __restrict__ enc, float* __restrict__ out)
{
    int i = blockIdx.x * blockDim.x + threadIdx.x;
    if (i >= Bb * 1024 * 64) return;
    int b   = i >> 16;
    int rem = i & 65535;
    int n2  = rem >> 6;
    int d2  = rem & 63;
    int gy2 = n2 >> 5, gx2 = n2 & 31;
    int py2 = d2 >> 3, px2 = d2 & 7;
    int y = gy2 * 8 + py2, x = gx2 * 8 + px2;
    int n1 = (y >> 4) * 16 + (x >> 4);
    int d1 = (y & 15) * 16 + (x & 15);
    out[i] = enc[((long)(b * 256 + n1)) * 256 + d1];
}

extern "C" void kernel_launch(void* const* d_in, const int* in_sizes, int n_in,
                              void* d_out, int out_size)
{
    (void)in_sizes; (void)n_in; (void)out_size;
    const float* X    = (const float*)d_in[0];
    const float* pos  = (const float*)d_in[1];
    const float* W_in = (const float*)d_in[2];
    const float* b_in = (const float*)d_in[3];
    const float* Wq   = (const float*)d_in[4];
    const float* bq   = (const float*)d_in[5];
    const float* Wk   = (const float*)d_in[6];
    const float* bk   = (const float*)d_in[7];
    const float* Wv   = (const float*)d_in[8];
    const float* bv   = (const float*)d_in[9];
    const float* Wo   = (const float*)d_in[10];
    const float* bo   = (const float*)d_in[11];
    const float* ln1g = (const float*)d_in[12];
    const float* ln1b = (const float*)d_in[13];
    const float* ln2g = (const float*)d_in[14];
    const float* ln2b = (const float*)d_in[15];
    const float* W1   = (const float*)d_in[16];
    const float* b1   = (const float*)d_in[17];
    const float* W2   = (const float*)d_in[18];
    const float* b2   = (const float*)d_in[19];
    float* out = (float*)d_out;

    float *patch, *enc, *encr, *qkv, *attn, *o, *a, *f1, *wop;
    float *wrin, *wrqkv, *wro, *wr1, *wr2, *bqkv;
    cudaGetSymbolAddress((void**)&patch, g_patch);
    cudaGetSymbolAddress((void**)&enc,   g_enc);
    cudaGetSymbolAddress((void**)&encr,  g_encr);
    cudaGetSymbolAddress((void**)&qkv,   g_qkv);
    cudaGetSymbolAddress((void**)&attn,  g_attn);
    cudaGetSymbolAddress((void**)&o,     g_o);
    cudaGetSymbolAddress((void**)&a,     g_a);
    cudaGetSymbolAddress((void**)&f1,    g_f1);
    cudaGetSymbolAddress((void**)&wop,   g_wop);
    cudaGetSymbolAddress((void**)&wrin,  g_wr_in);
    cudaGetSymbolAddress((void**)&wrqkv, g_wr_qkv);
    cudaGetSymbolAddress((void**)&wro,   g_wr_o);
    cudaGetSymbolAddress((void**)&wr1,   g_wr_1);
    cudaGetSymbolAddress((void**)&wr2,   g_wr_2);
    cudaGetSymbolAddress((void**)&bqkv,  g_bqkv);

    cudaFuncSetAttribute(mma_gemm_kernel<false, false, 0>, cudaFuncAttributeMaxDynamicSharedMemorySize, SMEM_GEMM);
    cudaFuncSetAttribute(mma_gemm_kernel<false, false, 1>, cudaFuncAttributeMaxDynamicSharedMemorySize, SMEM_GEMM);
    cudaFuncSetAttribute(mma_gemm_kernel<false, false, 2>, cudaFuncAttributeMaxDynamicSharedMemorySize, SMEM_GEMM);
    cudaFuncSetAttribute(mma_gemm_kernel<true,  false, 0>, cudaFuncAttributeMaxDynamicSharedMemorySize, SMEM_GEMM);
    cudaFuncSetAttribute(mma_gemm_kernel<false, true,  0>, cudaFuncAttributeMaxDynamicSharedMemorySize, SMEM_GEMM);
    cudaFuncSetAttribute(mma_gemm_kernel<false, true,  1>, cudaFuncAttributeMaxDynamicSharedMemorySize, SMEM_GEMM);

    const float scale = 1.0f / 16.0f;   // 1/sqrt(KD=256)

    round_copy_all_kernel<<<(int)((RCA_TOTAL4 + 255) / 256), 256>>>(
        W_in, wrin, Wq, Wk, Wv, wrqkv, Wo, wro, W1, wr1, W2, wr2);
    pack_bias_kernel<<<(LAY * QC3 + 255) / 256, 256>>>(bq, bk, bv, bqkv);

    patch_embed_kernel<<<(ROWS * D1 + 255) / 256, 256>>>(X, pos, patch);

    // enc = patch @ W_in + b_in  (dual: full enc + rounded encr)
    mma_gemm_kernel<false, false, 2><<<dim3(D1 / BN, ROWS / BM, 1), 256, SMEM_GEMM>>>(
        patch, wrin, b_in, enc, encr, D1, D1, D1, D1, 0, 0, 0, 0, 0, 0, 1, 1.f);

    for (int l = 0; l < LAY; l++) {
        const float* wqkv_l = wrqkv + (long)l * D1 * QC3;
        const float* bqkv_l = bqkv  + (long)l * QC3;
        const float* wo_l   = wro   + (long)l * QC * D1;
        const float* w1_l   = wr1   + (long)l * D1 * HID;
        const float* w2_l   = wr2   + (long)l * HID * D1;

        // qkv = encr @ [Wq|Wk|Wv] + [bq|bk|bv]  — single fused GEMM, N=6144
        mma_gemm_kernel<false, false, 1><<<dim3(QC3 / BN, ROWS / BM, 1), 256, SMEM_GEMM>>>(
            encr, wqkv_l, bqkv_l, qkv, nullptr, D1, D1, QC3, QC3, 0, 0, 0, 0, 0, 0, 1, 1.f);

        // logits[b,h,q,n] = scale * Q_bh @ K_bh^T   (q at col 0, k at col QC of qkv)
        mma_gemm_kernel<true, false, 0><<<dim3(N1 / BN, N1 / BM, Bb * NH), 256, SMEM_GEMM>>>(
            qkv, qkv + QC, nullptr, attn, nullptr, KD, QC3, QC3, N1,
            (long)N1 * QC3, KD, (long)N1 * QC3, KD,
            (long)NH * N1 * N1, (long)N1 * N1, NH, scale);

        softmax_kernel<<<(Bb * NH * N1) / 8, 256>>>(attn, Bb * NH * N1);

        // o = attn @ V   (v at col 2*QC of qkv)
        mma_gemm_kernel<false, false, 1><<<dim3(KD / BN, N1 / BM, Bb * NH), 256, SMEM_GEMM>>>(
            attn, qkv + 2 * QC, nullptr, o, nullptr, N1, N1, QC3, QC,
            (long)NH * N1 * N1, (long)N1 * N1,
            (long)N1 * QC3, KD,
            (long)N1 * QC, KD, NH, 1.f);

        // a = o @ Wo + bo  — split-K=2 (grid z = chunk), partials then reduce
        mma_gemm_kernel<false, false, 0><<<dim3(D1 / BN, ROWS / BM, 2), 256, SMEM_GEMM>>>(
            o, wo_l, nullptr, wop, nullptr, QC / 2, QC, D1, D1,
            0, QC / 2,                       // A: chunk offset in K (columns)
            0, (long)(QC / 2) * D1,          // B: chunk offset in rows
            0, (long)ROWS * D1,              // C: partial buffer stride
            2, 1.f);
        splitk_reduce_kernel<<<(ROWS * D1 / 4 + 255) / 256, 256>>>(wop, bo + (long)l * D1, a);

        add_ln_kernel<<<ROWS / 8, 256>>>(enc, encr, a, ln1g + (long)l * D1, ln1b + (long)l * D1);

        // f1 = gelu(encr @ W1 + b1)
        mma_gemm_kernel<false, true, 1><<<dim3(HID / BN, ROWS / BM, 1), 256, SMEM_GEMM>>>(
            encr, w1_l, b1 + (long)l * HID, f1, nullptr, D1, D1, HID, HID, 0, 0, 0, 0, 0, 0, 1, 1.f);
        // f2 = gelu(f1 @ W2 + b2)   (W2 is [HID, D1] row-major -> ldb = D1)
        mma_gemm_kernel<false, true, 0><<<dim3(D1 / BN, ROWS / BM, 1), 256, SMEM_GEMM>>>(
            f1, w2_l, b2 + (long)l * D1, a, nullptr, HID, HID, D1, D1, 0, 0, 0, 0, 0, 0, 1, 1.f);

        add_ln_kernel<<<ROWS / 8, 256>>>(enc, encr, a, ln2g + (long)l * D1, ln2b + (long)l * D1);
    }

    resample_kernel<<<(Bb * 1024 * 64 + 255) / 256, 256>>>(enc, out);
}